// round 4
// baseline (speedup 1.0000x reference)
#include <cuda_runtime.h>
#include <cuda_bf16.h>
#include <math.h>

#define B_  32
#define T_  512
#define D_  1024
#define UN_ 1024
#define NG_ 3072
#define M_  (B_*T_)
#define NBLK 128

typedef unsigned long long ull;

// ---------------- packed f32x2 helpers ----------------
#define FMA2(d, a, b) asm("fma.rn.f32x2 %0, %1, %2, %0;" : "+l"(d) : "l"(a), "l"(b))
#define ADD2(d, v)    asm("add.rn.f32x2 %0, %0, %1;"     : "+l"(d) : "l"(v))
#define DUP2(d, s)    asm("mov.b64 %0, {%1, %1};"        : "=l"(d) : "r"(s))

union F2U { ull u; float f[2]; };

// ---------------- device scratch ----------------
__device__ __align__(16) float g_xp[(size_t)M_ * NG_];        // 192 MB
__device__ __align__(16) float g_bsum[NG_];
__device__ __align__(16) float g_hbuf[2][B_ * UN_];
__device__ __align__(16) float g_p1[4 * B_ * UN_];            // slots: 0,1=z(ks) 2,3=r(ks)
__device__ __align__(16) float g_p2[4 * B_ * UN_];            // [ks2][b][u]
__device__ __align__(128) unsigned g_c1z[32];
__device__ __align__(128) unsigned g_c1r[32];
__device__ __align__(128) unsigned g_c2[32];
__device__ __align__(128) unsigned g_hdone[32];

// ---------------- bias column sums ----------------
__global__ void k_bsum(const float* __restrict__ b) {
    int c = blockIdx.x * 256 + threadIdx.x;
    float acc = 0.f;
    for (int k = 0; k < D_; k++) acc += b[(size_t)k * NG_ + c];
    g_bsum[c] = acc;
}

// ---------------- init: h0 -> hbuf[0], reset counters ----------------
__global__ void k_init(const float* __restrict__ h0) {
    int i = blockIdx.x * 256 + threadIdx.x;
    if (i < B_ * UN_) g_hbuf[0][i] = h0[i];
    if (blockIdx.x == 0 && threadIdx.x < 32) {
        g_c1z[threadIdx.x] = 0u;
        g_c1r[threadIdx.x] = 0u;
        g_c2[threadIdx.x]  = 0u;
        g_hdone[threadIdx.x] = 0u;
    }
}

// ---------------- SGEMM: xp = x @ W  (128x128 tile, 8x8/thread, f32x2) ----------------
__global__ void __launch_bounds__(256) k_gemm(const float* __restrict__ A,
                                              const float* __restrict__ Bm) {
    __shared__ float As[8][128];
    __shared__ float Bs[8][128];
    const int m0 = blockIdx.y * 128;
    const int n0 = blockIdx.x * 128;
    const int tx = threadIdx.x & 15;
    const int ty = threadIdx.x >> 4;
    const int aRow = threadIdx.x >> 1;
    const int aCol = (threadIdx.x & 1) * 4;
    const int bRow = threadIdx.x >> 5;
    const int bCol = (threadIdx.x & 31) * 4;

    ull acc2[8][4];
#pragma unroll
    for (int i = 0; i < 8; i++)
#pragma unroll
        for (int j = 0; j < 4; j++) acc2[i][j] = 0ULL;

    for (int k0 = 0; k0 < D_; k0 += 8) {
        float4 av = *(const float4*)(A + (size_t)(m0 + aRow) * D_ + k0 + aCol);
        As[aCol + 0][aRow] = av.x;
        As[aCol + 1][aRow] = av.y;
        As[aCol + 2][aRow] = av.z;
        As[aCol + 3][aRow] = av.w;
        *(float4*)&Bs[bRow][bCol] =
            *(const float4*)(Bm + (size_t)(k0 + bRow) * NG_ + n0 + bCol);
        __syncthreads();
#pragma unroll
        for (int kk = 0; kk < 8; kk++) {
            float a0[8];
            *(float4*)(a0)     = *(float4*)&As[kk][ty * 8];
            *(float4*)(a0 + 4) = *(float4*)&As[kk][ty * 8 + 4];
            ulonglong2 b01 = *(ulonglong2*)&Bs[kk][tx * 8];
            ulonglong2 b23 = *(ulonglong2*)&Bs[kk][tx * 8 + 4];
            ull bp[4] = {b01.x, b01.y, b23.x, b23.y};
#pragma unroll
            for (int i = 0; i < 8; i++) {
                ull ad; DUP2(ad, __float_as_uint(a0[i]));
#pragma unroll
                for (int j = 0; j < 4; j++) FMA2(acc2[i][j], ad, bp[j]);
            }
        }
        __syncthreads();
    }
#pragma unroll
    for (int i = 0; i < 8; i++) {
        size_t row = (size_t)(m0 + ty * 8 + i);
        ulonglong2 v0 = {acc2[i][0], acc2[i][1]};
        ulonglong2 v1 = {acc2[i][2], acc2[i][3]};
        *(ulonglong2*)&g_xp[row * NG_ + n0 + tx * 8]     = v0;
        *(ulonglong2*)&g_xp[row * NG_ + n0 + tx * 8 + 4] = v1;
    }
}

// ---------------- poll helper ----------------
__device__ __forceinline__ void pollge(const unsigned* p, unsigned tgt) {
    while (*((volatile const unsigned*)p) < tgt) { }
}

// ---------------- persistent GRU recurrence: polled dataflow ----------------
// smem floats: Ug[512*32]=16384 | Uh2[256*32]=8192 | hsT[128*32]=4096 | redu 7168
#define SM_UG   0
#define SM_UH2  16384
#define SM_HST  24576
#define SM_RED  28672
#define SM_FLOATS 35840

__global__ void __launch_bounds__(512, 1) k_gru(const float* __restrict__ U,
                                                float* __restrict__ out) {
    extern __shared__ float sm[];
    float* Ug  = sm + SM_UG;
    float* Uh2 = sm + SM_UH2;
    float* hsT = sm + SM_HST;
    ull*   redu = (ull*)(sm + SM_RED);

    const int bid = blockIdx.x, tid = threadIdx.x;
    // P1 role: gate g (0=z,1=r), u-tile 32, k-half 512
    const int g    = bid >> 6;
    const int ut   = (bid >> 1) & 31;
    const int ks   = bid & 1;
    const int u0p1 = ut * 32;
    const int k0p1 = ks * 512;
    const int slot1 = g * 2 + ks;
    // P2 role: u-tile 32, k-quarter 256
    const int ut2  = bid >> 2;
    const int ks2  = bid & 3;
    const int u0p2 = ut2 * 32;
    const int k0p2 = ks2 * 256;

    // preload U slices (resident all 512 steps)
    for (int i = tid; i < 512 * 8; i += 512) {
        int kk = i >> 3, uu4 = (i & 7) * 4;
        *(float4*)&Ug[kk * 32 + uu4] =
            *(const float4*)&U[(size_t)(k0p1 + kk) * NG_ + g * UN_ + u0p1 + uu4];
    }
    for (int i = tid; i < 256 * 8; i += 512) {
        int kk = i >> 3, uu4 = (i & 7) * 4;
        *(float4*)&Uh2[kk * 32 + uu4] =
            *(const float4*)&U[(size_t)(k0p2 + kk) * NG_ + 2 * UN_ + u0p2 + uu4];
    }
    __syncthreads();

    const int uq  = tid & 7;          // 4 u's at uq*4
    const int bq  = (tid >> 3) & 7;   // 4 b's at bq*4 (2 f32x2 pairs)
    const int kx  = tid >> 6;         // 8-way in-block k split
    const int r64 = tid & 63;

    for (int t = 0; t < T_; t++) {
        const float* hprev = g_hbuf[t & 1];
        float*       hnext = g_hbuf[(t + 1) & 1];

        // ================= P1: z or r partials =================
        ull acc2[2][4];
#pragma unroll
        for (int p = 0; p < 2; p++)
#pragma unroll
            for (int j = 0; j < 4; j++) acc2[p][j] = 0ULL;

        for (int kc = 0; kc < 4; kc++) {
            const int kbase = k0p1 + kc * 128;
            if (t) {
                const int tb = kbase >> 5;
#pragma unroll
                for (int j = 0; j < 4; j++) pollge(&g_hdone[tb + j], (unsigned)t);
            }
            __syncthreads();
            for (int i = tid; i < 1024; i += 512) {
                int b = i & 31, k4 = i >> 5;
                float4 hv = __ldcg((const float4*)&hprev[b * UN_ + kbase + k4 * 4]);
                hsT[(k4 * 4 + 0) * 32 + b] = hv.x;
                hsT[(k4 * 4 + 1) * 32 + b] = hv.y;
                hsT[(k4 * 4 + 2) * 32 + b] = hv.z;
                hsT[(k4 * 4 + 3) * 32 + b] = hv.w;
            }
            __syncthreads();
#pragma unroll 4
            for (int kk = kx; kk < 128; kk += 8) {
                float uv[4];
                *(float4*)uv = *(float4*)&Ug[(kc * 128 + kk) * 32 + uq * 4];
                ulonglong2 hp = *(ulonglong2*)&hsT[kk * 32 + bq * 4];
#pragma unroll
                for (int j = 0; j < 4; j++) {
                    ull dj; DUP2(dj, __float_as_uint(uv[j]));
                    FMA2(acc2[0][j], hp.x, dj);
                    FMA2(acc2[1][j], hp.y, dj);
                }
            }
        }
        __syncthreads();
        if (kx > 0) {
            ull* d = redu + (size_t)(kx - 1) * 8 * 64;
#pragma unroll
            for (int q = 0; q < 8; q++) d[q * 64 + r64] = acc2[q >> 2][q & 3];
        }
        __syncthreads();
        if (kx == 0) {
#pragma unroll
            for (int s = 0; s < 7; s++)
#pragma unroll
                for (int q = 0; q < 8; q++)
                    ADD2(acc2[q >> 2][q & 3], redu[(s * 8 + q) * 64 + r64]);
#pragma unroll
            for (int i = 0; i < 4; i++) {
                int p = i >> 1, hh = i & 1;
                F2U a0, a1, a2, a3;
                a0.u = acc2[p][0]; a1.u = acc2[p][1]; a2.u = acc2[p][2]; a3.u = acc2[p][3];
                float4 v = {a0.f[hh], a1.f[hh], a2.f[hh], a3.f[hh]};
                __stcg((float4*)&g_p1[(slot1 * B_ + bq * 4 + i) * UN_ + u0p1 + uq * 4], v);
            }
            __threadfence();
        }
        __syncthreads();
        if (tid == 0) atomicAdd(g == 0 ? &g_c1z[ut] : &g_c1r[ut], 1u);

        // ================= P2: hcand partials (rh fused into staging) =================
        ull a2v[2][4];
#pragma unroll
        for (int p = 0; p < 2; p++)
#pragma unroll
            for (int j = 0; j < 4; j++) a2v[p][j] = 0ULL;

        for (int kc = 0; kc < 2; kc++) {
            const int kbase = k0p2 + kc * 128;
            {
                const int tb = kbase >> 5;
                const unsigned tgt = 2u * (unsigned)(t + 1);
#pragma unroll
                for (int j = 0; j < 4; j++) pollge(&g_c1r[tb + j], tgt);
            }
            __syncthreads();
            for (int i = tid; i < 1024; i += 512) {
                int b = i & 31, k4 = i >> 5;
                int u = kbase + k4 * 4;
                float4 r0 = __ldcg((const float4*)&g_p1[(2 * B_ + b) * UN_ + u]);
                float4 r1 = __ldcg((const float4*)&g_p1[(3 * B_ + b) * UN_ + u]);
                float4 xv = __ldcg((const float4*)&g_xp[((size_t)b * T_ + t) * NG_ + UN_ + u]);
                float4 bb = *(const float4*)&g_bsum[UN_ + u];
                float4 hh = __ldcg((const float4*)&hprev[b * UN_ + u]);
                float s0 = r0.x + r1.x + xv.x + bb.x;
                float s1 = r0.y + r1.y + xv.y + bb.y;
                float s2 = r0.z + r1.z + xv.z + bb.z;
                float s3 = r0.w + r1.w + xv.w + bb.w;
                hsT[(k4 * 4 + 0) * 32 + b] = hh.x / (1.f + __expf(-s0));
                hsT[(k4 * 4 + 1) * 32 + b] = hh.y / (1.f + __expf(-s1));
                hsT[(k4 * 4 + 2) * 32 + b] = hh.z / (1.f + __expf(-s2));
                hsT[(k4 * 4 + 3) * 32 + b] = hh.w / (1.f + __expf(-s3));
            }
            __syncthreads();
#pragma unroll 4
            for (int kk = kx; kk < 128; kk += 8) {
                float uv[4];
                *(float4*)uv = *(float4*)&Uh2[(kc * 128 + kk) * 32 + uq * 4];
                ulonglong2 hp = *(ulonglong2*)&hsT[kk * 32 + bq * 4];
#pragma unroll
                for (int j = 0; j < 4; j++) {
                    ull dj; DUP2(dj, __float_as_uint(uv[j]));
                    FMA2(a2v[0][j], hp.x, dj);
                    FMA2(a2v[1][j], hp.y, dj);
                }
            }
        }
        __syncthreads();
        if (kx > 0) {
            ull* d = redu + (size_t)(kx - 1) * 8 * 64;
#pragma unroll
            for (int q = 0; q < 8; q++) d[q * 64 + r64] = a2v[q >> 2][q & 3];
        }
        __syncthreads();
        if (kx == 0) {
#pragma unroll
            for (int s = 0; s < 7; s++)
#pragma unroll
                for (int q = 0; q < 8; q++)
                    ADD2(a2v[q >> 2][q & 3], redu[(s * 8 + q) * 64 + r64]);
#pragma unroll
            for (int i = 0; i < 4; i++) {
                int p = i >> 1, hh = i & 1;
                F2U a0, a1, a2, a3;
                a0.u = a2v[p][0]; a1.u = a2v[p][1]; a2.u = a2v[p][2]; a3.u = a2v[p][3];
                float4 v = {a0.f[hh], a1.f[hh], a2.f[hh], a3.f[hh]};
                __stcg((float4*)&g_p2[(ks2 * B_ + bq * 4 + i) * UN_ + u0p2 + uq * 4], v);
            }
            __threadfence();
        }
        __syncthreads();
        if (tid == 0) atomicAdd(&g_c2[ut2], 1u);

        // ================= hn writer (one block per u-tile) =================
        if (ks2 == 0) {
            pollge(&g_c2[ut2], 4u * (unsigned)(t + 1));
            pollge(&g_c1z[ut2], 2u * (unsigned)(t + 1));
            for (int i = tid; i < 1024; i += 512) {
                int u = u0p2 + (i & 31), b = i >> 5;
                float hcs = __ldcg(&g_p2[(0 * B_ + b) * UN_ + u]) +
                            __ldcg(&g_p2[(1 * B_ + b) * UN_ + u]) +
                            __ldcg(&g_p2[(2 * B_ + b) * UN_ + u]) +
                            __ldcg(&g_p2[(3 * B_ + b) * UN_ + u]) +
                            __ldcg(&g_xp[((size_t)b * T_ + t) * NG_ + 2 * UN_ + u]) +
                            g_bsum[2 * UN_ + u];
                float zs  = __ldcg(&g_p1[(0 * B_ + b) * UN_ + u]) +
                            __ldcg(&g_p1[(1 * B_ + b) * UN_ + u]) +
                            __ldcg(&g_xp[((size_t)b * T_ + t) * NG_ + u]) +
                            g_bsum[u];
                float z  = 1.f / (1.f + __expf(-zs));
                float hc = tanhf(hcs);
                float ho = __ldcg(&hprev[b * UN_ + u]);
                float hn = z * ho + (1.f - z) * hc;
                __stcg(&hnext[b * UN_ + u], hn);
                out[((size_t)b * T_ + t) * UN_ + u] = hn;
            }
            __threadfence();
            __syncthreads();
            if (tid == 0) atomicAdd(&g_hdone[ut2], 1u);
        }
    }

    // final hidden state hT = hbuf[T&1] = hbuf[0]
    if (bid < 32) {
        pollge(&g_hdone[bid], (unsigned)T_);
        for (int i = tid; i < 1024; i += 512) {
            int u = bid * 32 + (i & 31), b = i >> 5;
            out[(size_t)B_ * T_ * UN_ + (size_t)b * UN_ + u] =
                __ldcg(&g_hbuf[0][b * UN_ + u]);
        }
    }
}

// ---------------- launcher ----------------
extern "C" void kernel_launch(void* const* d_in, const int* in_sizes, int n_in,
                              void* d_out, int out_size) {
    const float* x  = (const float*)d_in[0];
    const float* W  = (const float*)d_in[1];
    const float* U  = (const float*)d_in[2];
    const float* b  = (const float*)d_in[3];
    const float* h0 = (const float*)d_in[4];
    float* out = (float*)d_out;

    static bool attr_done = false;
    if (!attr_done) {
        cudaFuncSetAttribute(k_gru, cudaFuncAttributeMaxDynamicSharedMemorySize,
                             SM_FLOATS * sizeof(float));
        attr_done = true;
    }

    k_bsum<<<NG_ / 256, 256>>>(b);
    k_init<<<NBLK, 256>>>(h0);
    {
        dim3 grid(NG_ / 128, M_ / 128);
        k_gemm<<<grid, 256>>>(x, W);
    }
    k_gru<<<NBLK, 512, SM_FLOATS * sizeof(float)>>>(U, out);
}

// round 5
// speedup vs baseline: 1.2134x; 1.2134x over previous
#include <cuda_runtime.h>
#include <cuda_bf16.h>
#include <math.h>

#define B_  32
#define T_  512
#define D_  1024
#define UN_ 1024
#define NG_ 3072
#define M_  (B_*T_)
#define NBLK 128

typedef unsigned long long ull;

// ---------------- packed f32x2 helpers ----------------
#define FMA2(d, a, b) asm("fma.rn.f32x2 %0, %1, %2, %0;" : "+l"(d) : "l"(a), "l"(b))
#define ADD2(d, v)    asm("add.rn.f32x2 %0, %0, %1;"     : "+l"(d) : "l"(v))
#define DUP2(d, s)    asm("mov.b64 %0, {%1, %1};"        : "=l"(d) : "r"(s))

union F2U { ull u; float f[2]; };

// ---------------- device scratch ----------------
__device__ __align__(16) float g_xp[(size_t)M_ * NG_];      // 192 MB
__device__ __align__(16) float g_bsum[NG_];
__device__ __align__(16) float g_hbuf[2][B_ * UN_];
__device__ __align__(16) float g_z[B_ * UN_];
__device__ __align__(16) float g_rh[B_ * UN_];
__device__ __align__(128) unsigned g_s1;
__device__ __align__(128) unsigned g_s2;

// ---------------- bias column sums ----------------
__global__ void k_bsum(const float* __restrict__ b) {
    int c = blockIdx.x * 256 + threadIdx.x;
    float acc = 0.f;
    for (int k = 0; k < D_; k++) acc += b[(size_t)k * NG_ + c];
    g_bsum[c] = acc;
}

// ---------------- init ----------------
__global__ void k_init(const float* __restrict__ h0) {
    int i = blockIdx.x * 256 + threadIdx.x;
    if (i < B_ * UN_) g_hbuf[0][i] = h0[i];
    if (blockIdx.x == 0 && threadIdx.x == 0) { g_s1 = 0u; g_s2 = 0u; }
}

// ---------------- SGEMM: xp = x @ W (128x128 tile, f32x2) ----------------
__global__ void __launch_bounds__(256) k_gemm(const float* __restrict__ A,
                                              const float* __restrict__ Bm) {
    __shared__ float As[8][128];
    __shared__ float Bs[8][128];
    const int m0 = blockIdx.y * 128;
    const int n0 = blockIdx.x * 128;
    const int tx = threadIdx.x & 15;
    const int ty = threadIdx.x >> 4;
    const int aRow = threadIdx.x >> 1;
    const int aCol = (threadIdx.x & 1) * 4;
    const int bRow = threadIdx.x >> 5;
    const int bCol = (threadIdx.x & 31) * 4;

    ull acc2[8][4];
#pragma unroll
    for (int i = 0; i < 8; i++)
#pragma unroll
        for (int j = 0; j < 4; j++) acc2[i][j] = 0ULL;

    for (int k0 = 0; k0 < D_; k0 += 8) {
        float4 av = *(const float4*)(A + (size_t)(m0 + aRow) * D_ + k0 + aCol);
        As[aCol + 0][aRow] = av.x;
        As[aCol + 1][aRow] = av.y;
        As[aCol + 2][aRow] = av.z;
        As[aCol + 3][aRow] = av.w;
        *(float4*)&Bs[bRow][bCol] =
            *(const float4*)(Bm + (size_t)(k0 + bRow) * NG_ + n0 + bCol);
        __syncthreads();
#pragma unroll
        for (int kk = 0; kk < 8; kk++) {
            float a0[8];
            *(float4*)(a0)     = *(float4*)&As[kk][ty * 8];
            *(float4*)(a0 + 4) = *(float4*)&As[kk][ty * 8 + 4];
            ulonglong2 b01 = *(ulonglong2*)&Bs[kk][tx * 8];
            ulonglong2 b23 = *(ulonglong2*)&Bs[kk][tx * 8 + 4];
            ull bp[4] = {b01.x, b01.y, b23.x, b23.y};
#pragma unroll
            for (int i = 0; i < 8; i++) {
                ull ad; DUP2(ad, __float_as_uint(a0[i]));
#pragma unroll
                for (int j = 0; j < 4; j++) FMA2(acc2[i][j], ad, bp[j]);
            }
        }
        __syncthreads();
    }
#pragma unroll
    for (int i = 0; i < 8; i++) {
        size_t row = (size_t)(m0 + ty * 8 + i);
        ulonglong2 v0 = {acc2[i][0], acc2[i][1]};
        ulonglong2 v1 = {acc2[i][2], acc2[i][3]};
        *(ulonglong2*)&g_xp[row * NG_ + n0 + tx * 8]     = v0;
        *(ulonglong2*)&g_xp[row * NG_ + n0 + tx * 8 + 4] = v1;
    }
}

// ---------------- sync helper: one counter, tid0 polls ----------------
__device__ __forceinline__ void arrive_wait(unsigned* cnt, unsigned tgt) {
    __syncthreads();
    if (threadIdx.x == 0) {
        atomicAdd(cnt, 1u);
        while (*((volatile unsigned*)cnt) < tgt) { }
        __threadfence();
    }
    __syncthreads();
}

// ---------------- persistent GRU: block owns 8 u-cols, full k ----------------
// smem floats: Uzr[1024*16]=16384 | Uh[1024*8]=8192 | hsT[128*32]=4096 | red[8192]
#define SM_UZR  0
#define SM_UH   16384
#define SM_HST  24576
#define SM_RED  28672
#define SM_FLOATS 36864

__global__ void __launch_bounds__(512, 1) k_gru(const float* __restrict__ U,
                                                float* __restrict__ out) {
    extern __shared__ float sm[];
    float* Uzr = sm + SM_UZR;          // [k][16]: cols 0-7 = z(u0..), 8-15 = r(u0..)
    float* Uh  = sm + SM_UH;           // [k][8]
    float* hsT = sm + SM_HST;          // [128 k][32 b]
    ull*   red = (ull*)(sm + SM_RED);  // 4096 ull

    const int bid = blockIdx.x, tid = threadIdx.x;
    const int u0 = bid * 8;

    // load U slices (resident for all 512 steps)
    for (int i = tid; i < 4096; i += 512) {
        int k = i >> 2, q = i & 3;
        int col = (q < 2) ? (u0 + q * 4) : (UN_ + u0 + (q - 2) * 4);
        *(float4*)&Uzr[k * 16 + q * 4] = *(const float4*)&U[(size_t)k * NG_ + col];
    }
    for (int i = tid; i < 2048; i += 512) {
        int k = i >> 1, q = i & 1;
        *(float4*)&Uh[k * 8 + q * 4] =
            *(const float4*)&U[(size_t)k * NG_ + 2 * UN_ + u0 + q * 4];
    }
    __syncthreads();

    // P1 thread roles: 32 tiles (8 b-groups x 4 c-groups) x 16 k-segs
    const int tl1 = tid & 31;
    const int b41 = (tl1 & 7) * 4;
    const int c41 = (tl1 >> 3) * 4;
    const int sg1 = tid >> 5;           // 0..15, 8 k each per chunk
    // P2 thread roles: 16 tiles (8 b x 2 c) x 32 k-segs
    const int tl2 = tid & 15;
    const int b42 = (tl2 & 7) * 4;
    const int c42 = (tl2 >> 3) * 4;
    const int sg2 = tid >> 4;           // 0..31, 4 k each per chunk

    // staging slots: this thread loads float4 slots tid and tid+512 of 1024
    const int sb0 = tid & 31,        sk0 = tid >> 5;          // slot tid
    const int sb1 = (tid + 512) & 31, sk1 = (tid + 512) >> 5; // slot tid+512

    for (int t = 0; t < T_; t++) {
        const float* hprev = g_hbuf[t & 1];
        float*       hnext = g_hbuf[(t + 1) & 1];

        // ================= P1: z,r for this block's 8 u-cols, full k =================
        ull acc[2][4];
#pragma unroll
        for (int p = 0; p < 2; p++)
#pragma unroll
            for (int j = 0; j < 4; j++) acc[p][j] = 0ULL;

        float4 pa = *(const float4*)(hprev + sb0 * UN_ + sk0 * 4);
        float4 pb = *(const float4*)(hprev + sb1 * UN_ + sk1 * 4);
        for (int c = 0; c < 8; c++) {
            __syncthreads();
            hsT[(sk0 * 4 + 0) * 32 + sb0] = pa.x;
            hsT[(sk0 * 4 + 1) * 32 + sb0] = pa.y;
            hsT[(sk0 * 4 + 2) * 32 + sb0] = pa.z;
            hsT[(sk0 * 4 + 3) * 32 + sb0] = pa.w;
            hsT[(sk1 * 4 + 0) * 32 + sb1] = pb.x;
            hsT[(sk1 * 4 + 1) * 32 + sb1] = pb.y;
            hsT[(sk1 * 4 + 2) * 32 + sb1] = pb.z;
            hsT[(sk1 * 4 + 3) * 32 + sb1] = pb.w;
            __syncthreads();
            if (c < 7) {
                pa = *(const float4*)(hprev + sb0 * UN_ + (c + 1) * 128 + sk0 * 4);
                pb = *(const float4*)(hprev + sb1 * UN_ + (c + 1) * 128 + sk1 * 4);
            }
            const int kg = c * 128;
#pragma unroll
            for (int kk = 0; kk < 8; kk++) {
                int kl = sg1 * 8 + kk;
                ulonglong2 hp = *(ulonglong2*)&hsT[kl * 32 + b41];
                float uv[4];
                *(float4*)uv = *(float4*)&Uzr[(kg + kl) * 16 + c41];
#pragma unroll
                for (int j = 0; j < 4; j++) {
                    ull dj; DUP2(dj, __float_as_uint(uv[j]));
                    FMA2(acc[0][j], hp.x, dj);
                    FMA2(acc[1][j], hp.y, dj);
                }
            }
        }
        __syncthreads();
#pragma unroll
        for (int q = 0; q < 8; q++)
            red[(sg1 * 8 + q) * 32 + tl1] = acc[q >> 2][q & 3];
        __syncthreads();
        if (tid < 256) {
            int tile = tid & 31, q = tid >> 5;
            ull s = red[q * 32 + tile];
#pragma unroll
            for (int sg = 1; sg < 16; sg++) ADD2(s, red[(sg * 8 + q) * 32 + tile]);
            F2U v; v.u = s;
            int p = q >> 2, j = q & 3;
            int b0 = (tile & 7) * 4 + p * 2;
            int cc = (tile >> 3) * 4 + j;
#pragma unroll
            for (int e = 0; e < 2; e++) {
                int b = b0 + e;
                if (cc < 8) {
                    int u = u0 + cc;
                    float zs = v.f[e] + __ldcg(&g_xp[((size_t)b * T_ + t) * NG_ + u]) + g_bsum[u];
                    __stcg(&g_z[b * UN_ + u], 1.f / (1.f + __expf(-zs)));
                } else {
                    int u = u0 + cc - 8;
                    float rs = v.f[e] + __ldcg(&g_xp[((size_t)b * T_ + t) * NG_ + UN_ + u]) +
                               g_bsum[UN_ + u];
                    float r = 1.f / (1.f + __expf(-rs));
                    __stcg(&g_rh[b * UN_ + u], r * __ldcg(&hprev[b * UN_ + u]));
                }
            }
            __threadfence();
        }
        arrive_wait(&g_s1, (unsigned)NBLK * (t + 1));

        // ================= P2: hcand + hn for 8 u-cols, full k =================
        ull a2[2][4];
#pragma unroll
        for (int p = 0; p < 2; p++)
#pragma unroll
            for (int j = 0; j < 4; j++) a2[p][j] = 0ULL;

        pa = __ldcg((const float4*)(g_rh + sb0 * UN_ + sk0 * 4));
        pb = __ldcg((const float4*)(g_rh + sb1 * UN_ + sk1 * 4));
        for (int c = 0; c < 8; c++) {
            __syncthreads();
            hsT[(sk0 * 4 + 0) * 32 + sb0] = pa.x;
            hsT[(sk0 * 4 + 1) * 32 + sb0] = pa.y;
            hsT[(sk0 * 4 + 2) * 32 + sb0] = pa.z;
            hsT[(sk0 * 4 + 3) * 32 + sb0] = pa.w;
            hsT[(sk1 * 4 + 0) * 32 + sb1] = pb.x;
            hsT[(sk1 * 4 + 1) * 32 + sb1] = pb.y;
            hsT[(sk1 * 4 + 2) * 32 + sb1] = pb.z;
            hsT[(sk1 * 4 + 3) * 32 + sb1] = pb.w;
            __syncthreads();
            if (c < 7) {
                pa = __ldcg((const float4*)(g_rh + sb0 * UN_ + (c + 1) * 128 + sk0 * 4));
                pb = __ldcg((const float4*)(g_rh + sb1 * UN_ + (c + 1) * 128 + sk1 * 4));
            }
            const int kg = c * 128;
#pragma unroll
            for (int kk = 0; kk < 4; kk++) {
                int kl = sg2 * 4 + kk;
                ulonglong2 hp = *(ulonglong2*)&hsT[kl * 32 + b42];
                float uv[4];
                *(float4*)uv = *(float4*)&Uh[(kg + kl) * 8 + c42];
#pragma unroll
                for (int j = 0; j < 4; j++) {
                    ull dj; DUP2(dj, __float_as_uint(uv[j]));
                    FMA2(a2[0][j], hp.x, dj);
                    FMA2(a2[1][j], hp.y, dj);
                }
            }
        }
        __syncthreads();
#pragma unroll
        for (int q = 0; q < 8; q++)
            red[(sg2 * 8 + q) * 16 + tl2] = a2[q >> 2][q & 3];
        __syncthreads();
        if (tid < 128) {
            int tile = tid & 15, q = tid >> 4;
            ull s = red[q * 16 + tile];
#pragma unroll
            for (int sg = 1; sg < 32; sg++) ADD2(s, red[(sg * 8 + q) * 16 + tile]);
            F2U v; v.u = s;
            int p = q >> 2, j = q & 3;
            int b0 = (tile & 7) * 4 + p * 2;
            int u  = u0 + (tile >> 3) * 4 + j;
#pragma unroll
            for (int e = 0; e < 2; e++) {
                int b = b0 + e;
                float hcs = v.f[e] +
                            __ldcg(&g_xp[((size_t)b * T_ + t) * NG_ + 2 * UN_ + u]) +
                            g_bsum[2 * UN_ + u];
                float hc = tanhf(hcs);
                float z  = __ldcg(&g_z[b * UN_ + u]);
                float ho = __ldcg(&hprev[b * UN_ + u]);
                float hn = z * ho + (1.f - z) * hc;
                __stcg(&hnext[b * UN_ + u], hn);
                out[((size_t)b * T_ + t) * UN_ + u] = hn;
            }
            __threadfence();
        }
        arrive_wait(&g_s2, (unsigned)NBLK * (t + 1));
    }

    // final hidden state hT = hbuf[0] (T even)
    if (bid < 64) {
        int i = bid * 512 + tid;
        out[(size_t)M_ * UN_ + i] = __ldcg(&g_hbuf[0][i]);
    }
}

// ---------------- launcher ----------------
extern "C" void kernel_launch(void* const* d_in, const int* in_sizes, int n_in,
                              void* d_out, int out_size) {
    const float* x  = (const float*)d_in[0];
    const float* W  = (const float*)d_in[1];
    const float* U  = (const float*)d_in[2];
    const float* b  = (const float*)d_in[3];
    const float* h0 = (const float*)d_in[4];
    float* out = (float*)d_out;

    static bool attr_done = false;
    if (!attr_done) {
        cudaFuncSetAttribute(k_gru, cudaFuncAttributeMaxDynamicSharedMemorySize,
                             SM_FLOATS * sizeof(float));
        attr_done = true;
    }

    k_bsum<<<NG_ / 256, 256>>>(b);
    k_init<<<NBLK, 256>>>(h0);
    {
        dim3 grid(NG_ / 128, M_ / 128);
        k_gemm<<<grid, 256>>>(x, W);
    }
    k_gru<<<NBLK, 512, SM_FLOATS * sizeof(float)>>>(U, out);
}

// round 7
// speedup vs baseline: 2.1945x; 1.8086x over previous
#include <cuda_runtime.h>
#include <cuda_bf16.h>
#include <math.h>

#define B_  32
#define T_  512
#define D_  1024
#define UN_ 1024
#define NG_ 3072
#define M_  (B_*T_)
#define NBLK 128

typedef unsigned long long ull;

// ---------------- packed f32x2 helpers ----------------
#define FMA2(d, a, b) asm("fma.rn.f32x2 %0, %1, %2, %0;" : "+l"(d) : "l"(a), "l"(b))
#define ADD2(d, v)    asm("add.rn.f32x2 %0, %0, %1;"     : "+l"(d) : "l"(v))
#define DUP2(d, s)    asm("mov.b64 %0, {%1, %1};"        : "=l"(d) : "r"(s))

union F2U { ull u; float f[2]; };

// ---------------- cp.async helpers ----------------
__device__ __forceinline__ unsigned sptr(const void* p) {
    return (unsigned)__cvta_generic_to_shared(p);
}
#define CPA16(s, g)  asm volatile("cp.async.cg.shared.global [%0], [%1], 16;" :: "r"(s), "l"(g))
#define CPCOMMIT()   asm volatile("cp.async.commit_group;")
#define CPWAIT1()    asm volatile("cp.async.wait_group 1;")
#define CPWAIT0()    asm volatile("cp.async.wait_group 0;")

// ---------------- device scratch ----------------
__device__ __align__(16) float g_xp[(size_t)M_ * NG_];        // 192 MB [row][col]
__device__ __align__(16) float g_xpt[(size_t)T_ * NG_ * B_];  // 192 MB [t][col][b], bias folded
__device__ __align__(16) float g_bsum[NG_];
__device__ __align__(16) float g_hT[2][UN_ * B_];             // [u][b]
__device__ __align__(16) float g_rhT[UN_ * B_];               // [u][b]
__device__ __align__(128) unsigned g_s;

// ---------------- bias column sums ----------------
__global__ void k_bsum(const float* __restrict__ b) {
    int c = blockIdx.x * 256 + threadIdx.x;
    float acc = 0.f;
    for (int k = 0; k < D_; k++) acc += b[(size_t)k * NG_ + c];
    g_bsum[c] = acc;
}

// ---------------- init: h0 -> g_hT[0] transposed, reset counter ----------------
__global__ void k_init(const float* __restrict__ h0) {
    int i = blockIdx.x * 256 + threadIdx.x;
    if (i < B_ * UN_) {
        int u = i >> 5, b = i & 31;
        g_hT[0][i] = h0[b * UN_ + u];
    }
    if (blockIdx.x == 0 && threadIdx.x == 0) g_s = 0u;
}

// ---------------- SGEMM: xp = x @ W (128x128 tile, f32x2) ----------------
__global__ void __launch_bounds__(256) k_gemm(const float* __restrict__ A,
                                              const float* __restrict__ Bm) {
    __shared__ float As[8][128];
    __shared__ float Bs[8][128];
    const int m0 = blockIdx.y * 128;
    const int n0 = blockIdx.x * 128;
    const int tx = threadIdx.x & 15;
    const int ty = threadIdx.x >> 4;
    const int aRow = threadIdx.x >> 1;
    const int aCol = (threadIdx.x & 1) * 4;
    const int bRow = threadIdx.x >> 5;
    const int bCol = (threadIdx.x & 31) * 4;

    ull acc2[8][4];
#pragma unroll
    for (int i = 0; i < 8; i++)
#pragma unroll
        for (int j = 0; j < 4; j++) acc2[i][j] = 0ULL;

    for (int k0 = 0; k0 < D_; k0 += 8) {
        float4 av = *(const float4*)(A + (size_t)(m0 + aRow) * D_ + k0 + aCol);
        As[aCol + 0][aRow] = av.x;
        As[aCol + 1][aRow] = av.y;
        As[aCol + 2][aRow] = av.z;
        As[aCol + 3][aRow] = av.w;
        *(float4*)&Bs[bRow][bCol] =
            *(const float4*)(Bm + (size_t)(k0 + bRow) * NG_ + n0 + bCol);
        __syncthreads();
#pragma unroll
        for (int kk = 0; kk < 8; kk++) {
            float a0[8];
            *(float4*)(a0)     = *(float4*)&As[kk][ty * 8];
            *(float4*)(a0 + 4) = *(float4*)&As[kk][ty * 8 + 4];
            ulonglong2 b01 = *(ulonglong2*)&Bs[kk][tx * 8];
            ulonglong2 b23 = *(ulonglong2*)&Bs[kk][tx * 8 + 4];
            ull bp[4] = {b01.x, b01.y, b23.x, b23.y};
#pragma unroll
            for (int i = 0; i < 8; i++) {
                ull ad; DUP2(ad, __float_as_uint(a0[i]));
#pragma unroll
                for (int j = 0; j < 4; j++) FMA2(acc2[i][j], ad, bp[j]);
            }
        }
        __syncthreads();
    }
#pragma unroll
    for (int i = 0; i < 8; i++) {
        size_t row = (size_t)(m0 + ty * 8 + i);
        ulonglong2 v0 = {acc2[i][0], acc2[i][1]};
        ulonglong2 v1 = {acc2[i][2], acc2[i][3]};
        *(ulonglong2*)&g_xp[row * NG_ + n0 + tx * 8]     = v0;
        *(ulonglong2*)&g_xp[row * NG_ + n0 + tx * 8 + 4] = v1;
    }
}

// ---------------- transpose xp -> xpt [t][col][b], fold bias ----------------
__global__ void __launch_bounds__(256) k_xpt() {
    __shared__ float tile[128][33];
    const int t = blockIdx.y;
    const int col0 = blockIdx.x * 128;
    const int tid = threadIdx.x;
    const int b = tid & 31;
    const int cg = tid >> 5;      // 8 groups, 16 cols each
#pragma unroll
    for (int cc = 0; cc < 4; cc++) {
        int c = cg * 16 + cc * 4;
        float4 v = *(const float4*)&g_xp[((size_t)(b * T_ + t)) * NG_ + col0 + c];
        tile[c + 0][b] = v.x;
        tile[c + 1][b] = v.y;
        tile[c + 2][b] = v.z;
        tile[c + 3][b] = v.w;
    }
    __syncthreads();
    const int c = tid >> 1;
    const int half = tid & 1;
    const float bias = g_bsum[col0 + c];
    float* dst = &g_xpt[((size_t)t * NG_ + col0 + c) * B_ + half * 16];
#pragma unroll
    for (int j = 0; j < 4; j++) {
        float4 o;
        o.x = tile[c][half * 16 + j * 4 + 0] + bias;
        o.y = tile[c][half * 16 + j * 4 + 1] + bias;
        o.z = tile[c][half * 16 + j * 4 + 2] + bias;
        o.w = tile[c][half * 16 + j * 4 + 3] + bias;
        *(float4*)&dst[j * 4] = o;
    }
}

// ---------------- sync: one counter, tid0 polls ----------------
__device__ __forceinline__ void arrive_wait(unsigned tgt) {
    __syncthreads();
    if (threadIdx.x == 0) {
        atomicAdd(&g_s, 1u);
        while (*((volatile unsigned*)&g_s) < tgt) { }
        __threadfence();
    }
    __syncthreads();
}

// ---------------- persistent GRU ----------------
// smem floats:
//  Uzr [1024][16] = 16384 | Uh [1024][8] = 8192 | hst 3x4096 = 12288
//  red 8192 (4096 ull)    | xps 768 (xz|xr|xh)  | z_s 256 | hown 256
#define SM_UZR  0
#define SM_UH   16384
#define SM_HST  24576
#define SM_RED  36864
#define SM_XPS  45056
#define SM_ZS   45824
#define SM_HOWN 46080
#define SM_FLOATS 46336

__global__ void __launch_bounds__(512, 1) k_gru(const float* __restrict__ U,
                                                float* __restrict__ out) {
    extern __shared__ float sm[];
    float* Uzr  = sm + SM_UZR;
    float* Uh   = sm + SM_UH;
    float* hst  = sm + SM_HST;          // 3 bufs of [128k][32b]
    ull*   red  = (ull*)(sm + SM_RED);
    float* xps  = sm + SM_XPS;          // [0:256)=xz [256:512)=xr [512:768)=xh
    float* z_s  = sm + SM_ZS;           // [8u][32b]
    float* hown = sm + SM_HOWN;         // [8u][32b]

    const int bid = blockIdx.x, tid = threadIdx.x;
    const int u0 = bid * 8;

    // resident U slices
    for (int i = tid; i < 4096; i += 512) {
        int k = i >> 2, q = i & 3;
        int col = (q < 2) ? (u0 + q * 4) : (UN_ + u0 + (q - 2) * 4);
        *(float4*)&Uzr[k * 16 + q * 4] = *(const float4*)&U[(size_t)k * NG_ + col];
    }
    for (int i = tid; i < 2048; i += 512) {
        int k = i >> 1, q = i & 1;
        *(float4*)&Uh[k * 8 + q * 4] =
            *(const float4*)&U[(size_t)k * NG_ + 2 * UN_ + u0 + q * 4];
    }
    __syncthreads();

    // P1 roles
    const int tl1 = tid & 31;
    const int b41 = (tl1 & 7) * 4;
    const int c41 = (tl1 >> 3) * 4;
    const int sg1 = tid >> 5;
    // P2 roles
    const int tl2 = tid & 15;
    const int b42 = (tl2 & 7) * 4;
    const int c42 = (tl2 >> 3) * 4;
    const int sg2 = tid >> 4;

    for (int t = 0; t < T_; t++) {
        const float* hsrc = g_hT[t & 1];
        float*       hdst = g_hT[(t + 1) & 1];
        const float* xpt_t = g_xpt + (size_t)t * NG_ * B_;

        // ============ P1: z,r = sigmoid(xzr + h@Uzr) ============
        {
            const float* src = hsrc;                         // chunk 0
            CPA16(sptr(&hst[tid * 4]), src + tid * 4);
            CPA16(sptr(&hst[(tid + 512) * 4]), src + (tid + 512) * 4);
            if (tid < 64)
                CPA16(sptr(&xps[tid * 4]), xpt_t + (size_t)u0 * B_ + tid * 4);
            else if (tid < 128)
                CPA16(sptr(&xps[tid * 4]),                   // = 256 + (tid-64)*4
                      xpt_t + (size_t)(UN_ + u0) * B_ + (tid - 64) * 4);
            else if (tid < 192)
                CPA16(sptr(&hown[(tid - 128) * 4]), hsrc + (size_t)u0 * B_ + (tid - 128) * 4);
            CPCOMMIT();
            CPA16(sptr(&hst[4096 + tid * 4]), src + 4096 + tid * 4);
            CPA16(sptr(&hst[4096 + (tid + 512) * 4]), src + 4096 + (tid + 512) * 4);
            CPCOMMIT();
        }

        ull acc[2][4];
#pragma unroll
        for (int p = 0; p < 2; p++)
#pragma unroll
            for (int j = 0; j < 4; j++) acc[p][j] = 0ULL;

        for (int c = 0; c < 8; c++) {
            if (c < 7) CPWAIT1(); else CPWAIT0();
            __syncthreads();
            if (c + 2 < 8) {
                const float* src = hsrc + (c + 2) * 4096;
                float* dbuf = &hst[((c + 2) % 3) * 4096];
                CPA16(sptr(&dbuf[tid * 4]), src + tid * 4);
                CPA16(sptr(&dbuf[(tid + 512) * 4]), src + (tid + 512) * 4);
                CPCOMMIT();
            }
            const float* hb = &hst[(c % 3) * 4096];
            const int kg = c * 128;
#pragma unroll
            for (int kk = 0; kk < 8; kk++) {
                int kl = sg1 * 8 + kk;
                ulonglong2 hp = *(ulonglong2*)&hb[kl * 32 + b41];
                float uv[4];
                *(float4*)uv = *(float4*)&Uzr[(kg + kl) * 16 + c41];
#pragma unroll
                for (int j = 0; j < 4; j++) {
                    ull dj; DUP2(dj, __float_as_uint(uv[j]));
                    FMA2(acc[0][j], hp.x, dj);
                    FMA2(acc[1][j], hp.y, dj);
                }
            }
        }
        __syncthreads();
#pragma unroll
        for (int q = 0; q < 8; q++)
            red[(sg1 * 8 + q) * 32 + tl1] = acc[q >> 2][q & 3];
        __syncthreads();
        if (tid < 256) {
            int tile = tid & 31, q = tid >> 5;
            ull s = red[q * 32 + tile];
#pragma unroll
            for (int sg = 1; sg < 16; sg++) ADD2(s, red[(sg * 8 + q) * 32 + tile]);
            F2U v; v.u = s;
            int p = q >> 2, j = q & 3;
            int b0 = (tile & 7) * 4 + p * 2;
            int cc = (tile >> 3) * 4 + j;
            if (cc < 8) {
                float z0 = 1.f / (1.f + __expf(-(v.f[0] + xps[cc * 32 + b0])));
                float z1 = 1.f / (1.f + __expf(-(v.f[1] + xps[cc * 32 + b0 + 1])));
                *(float2*)&z_s[cc * 32 + b0] = make_float2(z0, z1);
            } else {
                int ul = cc - 8;
                float r0 = 1.f / (1.f + __expf(-(v.f[0] + xps[256 + ul * 32 + b0])));
                float r1 = 1.f / (1.f + __expf(-(v.f[1] + xps[256 + ul * 32 + b0 + 1])));
                float2 rh = make_float2(r0 * hown[ul * 32 + b0], r1 * hown[ul * 32 + b0 + 1]);
                __stcg((float2*)&g_rhT[(u0 + ul) * B_ + b0], rh);
            }
            if (cc >= 8) __threadfence();
        }
        arrive_wait((unsigned)NBLK * (2 * t + 1));

        // ============ P2: hc = tanh(xh + rh@Uh); hn ============
        {
            const float* src = g_rhT;                        // chunk 0
            CPA16(sptr(&hst[tid * 4]), src + tid * 4);
            CPA16(sptr(&hst[(tid + 512) * 4]), src + (tid + 512) * 4);
            if (tid < 64)
                CPA16(sptr(&xps[512 + tid * 4]),
                      xpt_t + (size_t)(2 * UN_ + u0) * B_ + tid * 4);
            CPCOMMIT();
            CPA16(sptr(&hst[4096 + tid * 4]), src + 4096 + tid * 4);
            CPA16(sptr(&hst[4096 + (tid + 512) * 4]), src + 4096 + (tid + 512) * 4);
            CPCOMMIT();
        }

        ull a2[2][4];
#pragma unroll
        for (int p = 0; p < 2; p++)
#pragma unroll
            for (int j = 0; j < 4; j++) a2[p][j] = 0ULL;

        for (int c = 0; c < 8; c++) {
            if (c < 7) CPWAIT1(); else CPWAIT0();
            __syncthreads();
            if (c + 2 < 8) {
                const float* src = g_rhT + (c + 2) * 4096;
                float* dbuf = &hst[((c + 2) % 3) * 4096];
                CPA16(sptr(&dbuf[tid * 4]), src + tid * 4);
                CPA16(sptr(&dbuf[(tid + 512) * 4]), src + (tid + 512) * 4);
                CPCOMMIT();
            }
            const float* hb = &hst[(c % 3) * 4096];
            const int kg = c * 128;
#pragma unroll
            for (int kk = 0; kk < 4; kk++) {
                int kl = sg2 * 4 + kk;
                ulonglong2 hp = *(ulonglong2*)&hb[kl * 32 + b42];
                float uv[4];
                *(float4*)uv = *(float4*)&Uh[(kg + kl) * 8 + c42];
#pragma unroll
                for (int j = 0; j < 4; j++) {
                    ull dj; DUP2(dj, __float_as_uint(uv[j]));
                    FMA2(a2[0][j], hp.x, dj);
                    FMA2(a2[1][j], hp.y, dj);
                }
            }
        }
        __syncthreads();
#pragma unroll
        for (int q = 0; q < 8; q++)
            red[(sg2 * 8 + q) * 16 + tl2] = a2[q >> 2][q & 3];
        __syncthreads();
        if (tid < 128) {
            int tile = tid & 15, q = tid >> 4;
            ull s = red[q * 16 + tile];
#pragma unroll
            for (int sg = 1; sg < 32; sg++) ADD2(s, red[(sg * 8 + q) * 16 + tile]);
            F2U v; v.u = s;
            int p = q >> 2, j = q & 3;
            int b0 = (tile & 7) * 4 + p * 2;
            int ul = (tile >> 3) * 4 + j;
            int u  = u0 + ul;
            float2 hn;
#pragma unroll
            for (int e = 0; e < 2; e++) {
                float hc = tanhf(v.f[e] + xps[512 + ul * 32 + b0 + e]);
                float z  = z_s[ul * 32 + b0 + e];
                float ho = hown[ul * 32 + b0 + e];
                float h  = z * ho + (1.f - z) * hc;
                ((float*)&hn)[e] = h;
                out[((size_t)(b0 + e) * T_ + t) * UN_ + u] = h;
            }
            __stcg((float2*)&hdst[u * B_ + b0], hn);
            __threadfence();
        }
        arrive_wait((unsigned)NBLK * (2 * t + 2));
    }

    // final hidden state hT (buffer 0, T even): out[b][u] layout
    if (bid < 64) {
        int i = bid * 512 + tid;          // i = u*32 + b
        int u = i >> 5, b = i & 31;
        out[(size_t)M_ * UN_ + (size_t)b * UN_ + u] = __ldcg(&g_hT[0][i]);
    }
}

// ---------------- launcher ----------------
extern "C" void kernel_launch(void* const* d_in, const int* in_sizes, int n_in,
                              void* d_out, int out_size) {
    const float* x  = (const float*)d_in[0];
    const float* W  = (const float*)d_in[1];
    const float* U  = (const float*)d_in[2];
    const float* b  = (const float*)d_in[3];
    const float* h0 = (const float*)d_in[4];
    float* out = (float*)d_out;

    static bool attr_done = false;
    if (!attr_done) {
        cudaFuncSetAttribute(k_gru, cudaFuncAttributeMaxDynamicSharedMemorySize,
                             SM_FLOATS * sizeof(float));
        attr_done = true;
    }

    k_bsum<<<NG_ / 256, 256>>>(b);
    k_init<<<NBLK, 256>>>(h0);
    {
        dim3 grid(NG_ / 128, M_ / 128);
        k_gemm<<<grid, 256>>>(x, W);
    }
    {
        dim3 grid(NG_ / 128, T_);
        k_xpt<<<grid, 256>>>();
    }
    k_gru<<<NBLK, 512, SM_FLOATS * sizeof(float)>>>(U, out);
}